// round 7
// baseline (speedup 1.0000x reference)
#include <cuda_runtime.h>
#include <cuda_bf16.h>
#include <cstdint>

// ===================== constants =====================
#define NTOK   16384
#define DIM    512
#define MARGIN 0.1f
#define QSCALE 16.0f                 // pre-quantization scale for e4m3
// logits = acc * (1/T) / QSCALE^2
#define INV_TS (14.285714285714286f / (16.0f * 16.0f))

#define KC     128                   // K-chunk (fp8 elems) per stage = 128 bytes/row
#define NK     (DIM / KC)            // 4 chunks
#define STAGE_BYTES (2 * 128 * KC)   // A tile + B tile per stage = 32KB
#define TILE_BYTES  (128 * KC)       // 16KB each

typedef unsigned long long u64;

// ===================== device globals (no cudaMalloc allowed) =====================
__device__ uint8_t g_sn[(size_t)NTOK * DIM];   // e4m3, scaled by QSCALE
__device__ uint8_t g_tn[(size_t)NTOK * DIM];
__device__ float g_diag[NTOK];                 // exact fp32 diagonal cos-sims
__device__ double g_sum;

// ===================== helpers =====================
__device__ __forceinline__ uint32_t smem_u32(const void* p) {
    uint32_t a;
    asm("{ .reg .u64 t; cvta.to.shared.u64 t, %1; cvt.u32.u64 %0, t; }" : "=r"(a) : "l"(p));
    return a;
}
__device__ __forceinline__ void cp_async16(uint32_t smem, const void* gmem) {
    asm volatile("cp.async.cg.shared.global [%0], [%1], 16;" :: "r"(smem), "l"(gmem));
}
#define CP_COMMIT() asm volatile("cp.async.commit_group;" ::: "memory")
#define CP_WAIT(n)  asm volatile("cp.async.wait_group %0;" :: "n"(n) : "memory")

__device__ __forceinline__ void ldsm4(uint32_t* r, uint32_t addr) {
    asm volatile("ldmatrix.sync.aligned.m8n8.x4.shared.b16 {%0,%1,%2,%3}, [%4];"
                 : "=r"(r[0]), "=r"(r[1]), "=r"(r[2]), "=r"(r[3]) : "r"(addr));
}
// fp8 e4m3 MMA: fragments are byte-identical to the (validated) bf16 m16n8k16 path
__device__ __forceinline__ void mma16832(float* c, const uint32_t* a, uint32_t b0, uint32_t b1) {
    asm volatile(
        "mma.sync.aligned.m16n8k32.row.col.f32.e4m3.e4m3.f32 "
        "{%0,%1,%2,%3}, {%4,%5,%6,%7}, {%8,%9}, {%0,%1,%2,%3};"
        : "+f"(c[0]), "+f"(c[1]), "+f"(c[2]), "+f"(c[3])
        : "r"(a[0]), "r"(a[1]), "r"(a[2]), "r"(a[3]), "r"(b0), "r"(b1));
}

// SW128 swizzle: 128B rows -> conflict-free ldmatrix + cp.async stores
#define SWZ(off) ((off) ^ (((off) >> 3) & 0x70))

// ===================== packed f32x2 helpers =====================
__device__ __forceinline__ u64 pfma(u64 a, u64 b, u64 c) {
    u64 d; asm("fma.rn.f32x2 %0, %1, %2, %3;" : "=l"(d) : "l"(a), "l"(b), "l"(c)); return d;
}
__device__ __forceinline__ u64 pmul(u64 a, u64 b) {
    u64 d; asm("mul.rn.f32x2 %0, %1, %2;" : "=l"(d) : "l"(a), "l"(b)); return d;
}
__device__ __forceinline__ u64 padd(u64 a, u64 b) {
    u64 d; asm("add.rn.f32x2 %0, %1, %2;" : "=l"(d) : "l"(a), "l"(b)); return d;
}
__device__ __forceinline__ u64 pack2(float lo, float hi) {
    u64 d; asm("mov.b64 %0, {%1, %2};" : "=l"(d) : "f"(lo), "f"(hi)); return d;
}
__device__ __forceinline__ void unpack2(uint32_t& lo, uint32_t& hi, u64 x) {
    asm("mov.b64 {%0, %1}, %2;" : "=r"(lo), "=r"(hi) : "l"(x));
}
__device__ __forceinline__ u64 bcast(float v) {
    uint32_t b = __float_as_uint(v);
    return ((u64)b << 32) | b;
}

// ===================== scalar softplus (accurate; finalize only) =====================
__device__ __forceinline__ float softplus_fast(float x) {
    float ax = fminf(fabsf(x), 20.0f);
    float r  = fmaxf(x, 0.0f);
    float t  = ax * -1.4426950408889634f;
    float kf = t + 12582912.0f;
    int   sc = __float_as_int(kf) << 23;
    float f  = t - (kf - 12582912.0f);
    float p  = 1.3333558146e-3f;
    p = fmaf(p, f, 9.6181291918e-3f);
    p = fmaf(p, f, 5.5504108664e-2f);
    p = fmaf(p, f, 2.4022650696e-1f);
    p = fmaf(p, f, 6.9314718056e-1f);
    p = fmaf(p, f, 1.0f);
    float e = __int_as_float(__float_as_int(p) + sc);
    float d = e + 2.0f;
    float y = fmaf(d, -0.16666667f, 0.83333333f);
    y = y * fmaf(-d, y, 2.0f);
    y = y * fmaf(-d, y, 2.0f);
    float z  = e * y;
    float z2 = z * z;
    float q  = 0.22222222f;
    q = fmaf(q, z2, 0.28571429f);
    q = fmaf(q, z2, 0.4f);
    q = fmaf(q, z2, 0.66666667f);
    q = fmaf(q, z2, 2.0f);
    return fmaf(z, q, r);
}

// ===================== kernel 1: L2-normalize rows + diag dot, fp32 -> e4m3*16 =====================
__global__ __launch_bounds__(256) void normalize_kernel(const float* __restrict__ S,
                                                        const float* __restrict__ T) {
    int row = blockIdx.x;
    int tid = threadIdx.x;
    if (row == 0 && tid == 0) g_sum = 0.0;

    const float2* s2 = (const float2*)(S + (size_t)row * DIM);
    const float2* t2 = (const float2*)(T + (size_t)row * DIM);
    float2 sv = s2[tid];
    float2 tv = t2[tid];
    float a = fmaf(sv.x, sv.x, sv.y * sv.y);
    float b = fmaf(tv.x, tv.x, tv.y * tv.y);
    float c = fmaf(sv.x, tv.x, sv.y * tv.y);
    #pragma unroll
    for (int o = 16; o; o >>= 1) {
        a += __shfl_xor_sync(0xffffffffu, a, o);
        b += __shfl_xor_sync(0xffffffffu, b, o);
        c += __shfl_xor_sync(0xffffffffu, c, o);
    }
    __shared__ float sa[8], sb[8], sc[8];
    int w = tid >> 5, l = tid & 31;
    if (l == 0) { sa[w] = a; sb[w] = b; sc[w] = c; }
    __syncthreads();
    float ta = 0.f, tb = 0.f, tc = 0.f;
    #pragma unroll
    for (int i = 0; i < 8; i++) { ta += sa[i]; tb += sb[i]; tc += sc[i]; }
    float ia = rsqrtf(ta) * QSCALE;
    float ib = rsqrtf(tb) * QSCALE;
    if (tid == 0) g_diag[row] = tc * rsqrtf(ta) * rsqrtf(tb);

    unsigned short so, to;
    float sx = sv.x * ia, sy = sv.y * ia;
    float tx = tv.x * ib, ty = tv.y * ib;
    // cvt d, a, b packs a->high byte, b->low byte
    asm("cvt.rn.satfinite.e4m3x2.f32 %0, %1, %2;" : "=h"(so) : "f"(sy), "f"(sx));
    asm("cvt.rn.satfinite.e4m3x2.f32 %0, %1, %2;" : "=h"(to) : "f"(ty), "f"(tx));
    ((unsigned short*)g_sn)[(size_t)row * (DIM / 2) + tid] = so;
    ((unsigned short*)g_tn)[(size_t)row * (DIM / 2) + tid] = to;
}

// ===================== kernel 2: fp8 mma.sync GEMM + fused packed-softplus sum =====================
// CTA tile 128x128, 4 warps (2x2), warp tile 64x64, double-buffered cp.async, 2 CTAs/SM.
__global__ __launch_bounds__(128, 2) void gemm_loss_kernel() {
    extern __shared__ uint8_t dynsmem[];
    __shared__ float s_red[4];

    int tid  = threadIdx.x;
    int wid  = tid >> 5;
    int lane = tid & 31;

    uint32_t sbase = smem_u32(dynsmem);

    // tile mapping with 8-row bands (L2 locality)
    int bid  = blockIdx.x;
    int band = bid >> 10;
    int rem  = bid & 1023;
    int br   = (band << 3) + (rem & 7);
    int bc   = rem >> 3;

    // ---- cp.async setup: per thread 8 A-segs + 8 B-segs of 16B per stage ----
    const uint8_t* gA = g_sn + (size_t)br * 128 * DIM;
    const uint8_t* gB = g_tn + (size_t)bc * 128 * DIM;
    uint32_t soff[8];
    uint32_t gofs[8];
    #pragma unroll
    for (int i = 0; i < 8; i++) {
        int idx = tid + (i << 7);        // 0..1023
        int r   = idx >> 3;              // row 0..127
        int sg  = idx & 7;               // 16B segment
        soff[i] = SWZ((r << 7) + (sg << 4));
        gofs[i] = r * DIM + (sg << 4);
    }

    // ---- ldmatrix address components (byte-identical to validated bf16 path) ----
    int wm = wid & 1;        // M half (64 rows)
    int wn = wid >> 1;       // N half (64 cols)
    int aRowB = (wm << 6) + (lane & 15);
    int aKsel = (lane >> 4) << 4;
    int bRowB = (wn << 6) + (lane & 7) + ((lane & 16) >> 1);
    int bKsel = (lane & 8) << 1;

    float acc[128];
    #pragma unroll
    for (int i = 0; i < 128; i++) acc[i] = 0.f;

    // ---- prologue: stage 0 ----
    {
        uint32_t sA = sbase, sB = sbase + TILE_BYTES;
        #pragma unroll
        for (int i = 0; i < 8; i++) cp_async16(sA + soff[i], gA + gofs[i]);
        #pragma unroll
        for (int i = 0; i < 8; i++) cp_async16(sB + soff[i], gB + gofs[i]);
        CP_COMMIT();
    }

    // ---- mainloop: 4 chunks of K=128 fp8 ----
    for (int c = 0; c < NK; ++c) {
        if (c + 1 < NK) {
            uint32_t st = (uint32_t)((c + 1) & 1) * STAGE_BYTES;
            uint32_t sA = sbase + st, sB = sA + TILE_BYTES;
            uint32_t gk = (uint32_t)(c + 1) * KC;
            #pragma unroll
            for (int i = 0; i < 8; i++) cp_async16(sA + soff[i], gA + gofs[i] + gk);
            #pragma unroll
            for (int i = 0; i < 8; i++) cp_async16(sB + soff[i], gB + gofs[i] + gk);
            CP_COMMIT();
            CP_WAIT(1);
        } else {
            CP_WAIT(0);
        }
        __syncthreads();

        uint32_t aBase = sbase + (uint32_t)(c & 1) * STAGE_BYTES;
        uint32_t bBase = aBase + TILE_BYTES;

        #pragma unroll
        for (int ks = 0; ks < KC / 32; ++ks) {    // 4 k32 steps, 32B each
            uint32_t a[4][4];
            #pragma unroll
            for (int mi = 0; mi < 4; ++mi) {
                int row = aRowB + (mi << 4);
                uint32_t kb = (uint32_t)(aKsel + (ks << 5));
                ldsm4(a[mi], aBase + (row << 7) + (kb ^ ((row & 7) << 4)));
            }
            #pragma unroll
            for (int nb = 0; nb < 4; ++nb) {
                uint32_t b[4];
                int row = bRowB + (nb << 4);
                uint32_t kb = (uint32_t)(bKsel + (ks << 5));
                ldsm4(b, bBase + (row << 7) + (kb ^ ((row & 7) << 4)));
                #pragma unroll
                for (int mi = 0; mi < 4; ++mi) {
                    mma16832(&acc[((mi << 3) + (nb << 1)) << 2],     a[mi], b[0], b[1]);
                    mma16832(&acc[((mi << 3) + (nb << 1) + 1) << 2], a[mi], b[2], b[3]);
                }
            }
        }
        __syncthreads();
    }

    // ---- fused epilogue: packed softplus + sum (diagonal corrected in finalize) ----
    const u64 c_invT   = bcast(INV_TS);
    const u64 c_negM   = bcast(-MARGIN);
    const u64 c_negL2E = bcast(-1.4426950408889634f);
    const u64 c_magic  = bcast(12582912.0f);
    const u64 c_nmagic = bcast(-12582912.0f);
    const u64 c_neg1   = bcast(-1.0f);
    const u64 c_neg2   = bcast(-2.0f);
    const u64 c_two    = bcast(2.0f);
    const u64 c_p4     = bcast(9.6181291918e-3f);
    const u64 c_p3     = bcast(5.5504108664e-2f);
    const u64 c_p2     = bcast(2.4022650696e-1f);
    const u64 c_p1     = bcast(6.9314718056e-1f);
    const u64 c_one    = bcast(1.0f);
    const u64 c_16     = bcast(0.16666667f);
    const u64 c_56     = bcast(0.83333333f);
    const u64 c_q3     = bcast(0.28571429f);
    const u64 c_q2     = bcast(0.4f);
    const u64 c_q1     = bcast(0.66666667f);

    u64 accL = 0ull;   // sum of log1p(exp(-|x|)) pairs
    u64 accS = 0ull;   // sum of (x + |x|) pairs

    #pragma unroll
    for (int i = 0; i < 64; i++) {
        u64 pa = pack2(acc[2 * i], acc[2 * i + 1]);
        u64 x  = pfma(pa, c_invT, c_negM);
        u64 ax = x & 0x7FFFFFFF7FFFFFFFull;
        u64 t  = pmul(ax, c_negL2E);
        u64 kf = padd(t, c_magic);
        u64 d1 = padd(kf, c_nmagic);
        u64 f  = pfma(d1, c_neg1, t);
        u64 p  = pfma(c_p4, f, c_p3);
        p = pfma(p, f, c_p2);
        p = pfma(p, f, c_p1);
        p = pfma(p, f, c_one);
        uint32_t klo, khi, plo, phi;
        unpack2(klo, khi, kf);
        unpack2(plo, phi, p);
        plo += klo << 23;
        phi += khi << 23;
        u64 e; asm("mov.b64 %0, {%1, %2};" : "=l"(e) : "r"(plo), "r"(phi));
        u64 nd = pfma(e, c_neg1, c_neg2);
        u64 y  = pfma(nd, c_16, c_56);
        u64 w  = pfma(nd, y, c_two); y = pmul(y, w);
        w      = pfma(nd, y, c_two); y = pmul(y, w);
        u64 z  = pmul(e, y);
        u64 z2 = pmul(z, z);
        u64 q  = pfma(c_q3, z2, c_q2);
        q = pfma(q, z2, c_q1);
        q = pfma(q, z2, c_two);
        accL = pfma(z, q, accL);
        accS = padd(accS, x);
        accS = padd(accS, ax);
    }

    uint32_t slo, shi, llo, lhi;
    unpack2(slo, shi, accS);
    unpack2(llo, lhi, accL);
    float sum = __uint_as_float(llo) + __uint_as_float(lhi);
    sum = fmaf(__uint_as_float(slo) + __uint_as_float(shi), 0.5f, sum);

    #pragma unroll
    for (int o = 16; o; o >>= 1) sum += __shfl_xor_sync(0xffffffffu, sum, o);
    if (lane == 0) s_red[wid] = sum;
    __syncthreads();
    if (tid == 0) {
        float s = s_red[0] + s_red[1] + s_red[2] + s_red[3];
        atomicAdd(&g_sum, (double)s);
    }
}

// ===================== kernel 3: diagonal correction + finalize =====================
// GEMM summed softplus(l-M) for ALL elements (incl. diagonal with fp8 logits).
// Correct: + softplus(-l_fp32 - M) - softplus(l_fp32 - M) per diagonal element.
// (fp8-vs-fp32 mismatch on just 16384 diagonal terms is ~2e-6 relative.)
__global__ __launch_bounds__(256) void finalize_kernel(float* out) {
    __shared__ float s_red[8];
    int tid = threadIdx.x;
    float corr = 0.f;
    for (int i = tid; i < NTOK; i += 256) {
        float l = g_diag[i] * 14.285714285714286f;
        corr += softplus_fast(-l - MARGIN) - softplus_fast(l - MARGIN);
    }
    #pragma unroll
    for (int o = 16; o; o >>= 1) corr += __shfl_xor_sync(0xffffffffu, corr, o);
    int w = tid >> 5, l = tid & 31;
    if (l == 0) s_red[w] = corr;
    __syncthreads();
    if (tid == 0) {
        float tc = 0.f;
        #pragma unroll
        for (int i = 0; i < 8; i++) tc += s_red[i];
        out[0] = (float)((g_sum + (double)tc) * (1.0 / (double)NTOK));
    }
}

// ===================== launch =====================
extern "C" void kernel_launch(void* const* d_in, const int* in_sizes, int n_in,
                              void* d_out, int out_size) {
    const float* S = (const float*)d_in[0];
    const float* T = (const float*)d_in[1];
    cudaFuncSetAttribute(gemm_loss_kernel,
                         cudaFuncAttributeMaxDynamicSharedMemorySize, 2 * STAGE_BYTES);
    normalize_kernel<<<NTOK, 256>>>(S, T);
    gemm_loss_kernel<<<(NTOK / 128) * (NTOK / 128), 128, 2 * STAGE_BYTES>>>();
    finalize_kernel<<<1, 256>>>((float*)d_out);
}

// round 9
// speedup vs baseline: 1.1389x; 1.1389x over previous
#include <cuda_runtime.h>
#include <cuda_bf16.h>
#include <cstdint>

// ===================== constants =====================
#define NTOK   16384
#define DIM    512
#define INV_T  14.285714285714286f   // 1/0.07
#define MARGIN 0.1f

#define GRIDX   2048                 // CTAs; each does 8 row-tiles, fixed col-tile
#define NTILES  16384
#define B_BYTES 131072               // resident B: 8 chunks x 16KB
#define A_STAGE 16384                // one A stage (128 rows x 128B)
#define SMEM_SZ (B_BYTES + 2 * A_STAGE + 1024)

typedef unsigned long long u64;

// ===================== device globals (no cudaMalloc allowed) =====================
__device__ __nv_bfloat16 g_sn[(size_t)NTOK * DIM];
__device__ __nv_bfloat16 g_tn[(size_t)NTOK * DIM];
__device__ float g_diag[NTOK];
__device__ double g_sum;

// ===================== helpers =====================
__device__ __forceinline__ uint32_t smem_u32(const void* p) {
    uint32_t a;
    asm("{ .reg .u64 t; cvta.to.shared.u64 t, %1; cvt.u32.u64 %0, t; }" : "=r"(a) : "l"(p));
    return a;
}
__device__ __forceinline__ void cp_async16(uint32_t smem, const void* gmem) {
    asm volatile("cp.async.cg.shared.global [%0], [%1], 16;" :: "r"(smem), "l"(gmem));
}
#define CP_COMMIT() asm volatile("cp.async.commit_group;" ::: "memory")
#define CP_WAIT(n)  asm volatile("cp.async.wait_group %0;" :: "n"(n) : "memory")

__device__ __forceinline__ void ldsm4(uint32_t* r, uint32_t addr) {
    asm volatile("ldmatrix.sync.aligned.m8n8.x4.shared.b16 {%0,%1,%2,%3}, [%4];"
                 : "=r"(r[0]), "=r"(r[1]), "=r"(r[2]), "=r"(r[3]) : "r"(addr));
}
__device__ __forceinline__ void mma16816(float* c, const uint32_t* a, uint32_t b0, uint32_t b1) {
    asm volatile(
        "mma.sync.aligned.m16n8k16.row.col.f32.bf16.bf16.f32 "
        "{%0,%1,%2,%3}, {%4,%5,%6,%7}, {%8,%9}, {%0,%1,%2,%3};"
        : "+f"(c[0]), "+f"(c[1]), "+f"(c[2]), "+f"(c[3])
        : "r"(a[0]), "r"(a[1]), "r"(a[2]), "r"(a[3]), "r"(b0), "r"(b1));
}
#define SWZ(off) ((off) ^ (((off) >> 3) & 0x70))

// ===================== packed f32x2 helpers =====================
__device__ __forceinline__ u64 pfma(u64 a, u64 b, u64 c) {
    u64 d; asm("fma.rn.f32x2 %0, %1, %2, %3;" : "=l"(d) : "l"(a), "l"(b), "l"(c)); return d;
}
__device__ __forceinline__ u64 pmul(u64 a, u64 b) {
    u64 d; asm("mul.rn.f32x2 %0, %1, %2;" : "=l"(d) : "l"(a), "l"(b)); return d;
}
__device__ __forceinline__ u64 padd(u64 a, u64 b) {
    u64 d; asm("add.rn.f32x2 %0, %1, %2;" : "=l"(d) : "l"(a), "l"(b)); return d;
}
__device__ __forceinline__ u64 pack2(float lo, float hi) {
    u64 d; asm("mov.b64 %0, {%1, %2};" : "=l"(d) : "f"(lo), "f"(hi)); return d;
}
__device__ __forceinline__ void unpack2(uint32_t& lo, uint32_t& hi, u64 x) {
    asm("mov.b64 {%0, %1}, %2;" : "=r"(lo), "=r"(hi) : "l"(x));
}
__device__ __forceinline__ u64 bcast(float v) {
    uint32_t b = __float_as_uint(v);
    return ((u64)b << 32) | b;
}

// ===================== scalar softplus (accurate; finalize only) =====================
__device__ __forceinline__ float softplus_fast(float x) {
    float ax = fminf(fabsf(x), 20.0f);
    float r  = fmaxf(x, 0.0f);
    float t  = ax * -1.4426950408889634f;
    float kf = t + 12582912.0f;
    int   sc = __float_as_int(kf) << 23;
    float f  = t - (kf - 12582912.0f);
    float p  = 1.3333558146e-3f;
    p = fmaf(p, f, 9.6181291918e-3f);
    p = fmaf(p, f, 5.5504108664e-2f);
    p = fmaf(p, f, 2.4022650696e-1f);
    p = fmaf(p, f, 6.9314718056e-1f);
    p = fmaf(p, f, 1.0f);
    float e = __int_as_float(__float_as_int(p) + sc);
    float d = e + 2.0f;
    float y = fmaf(d, -0.16666667f, 0.83333333f);
    y = y * fmaf(-d, y, 2.0f);
    y = y * fmaf(-d, y, 2.0f);
    float z  = e * y;
    float z2 = z * z;
    float q  = 0.22222222f;
    q = fmaf(q, z2, 0.28571429f);
    q = fmaf(q, z2, 0.4f);
    q = fmaf(q, z2, 0.66666667f);
    q = fmaf(q, z2, 2.0f);
    return fmaf(z, q, r);
}

// ===================== kernel 1: L2-normalize rows + diag dot, fp32 -> bf16 =====================
__global__ __launch_bounds__(256) void normalize_kernel(const float* __restrict__ S,
                                                        const float* __restrict__ T) {
    int row = blockIdx.x;
    int tid = threadIdx.x;
    if (row == 0 && tid == 0) g_sum = 0.0;

    const float2* s2 = (const float2*)(S + (size_t)row * DIM);
    const float2* t2 = (const float2*)(T + (size_t)row * DIM);
    float2 sv = s2[tid];
    float2 tv = t2[tid];
    float a = fmaf(sv.x, sv.x, sv.y * sv.y);
    float b = fmaf(tv.x, tv.x, tv.y * tv.y);
    float c = fmaf(sv.x, tv.x, sv.y * tv.y);
    #pragma unroll
    for (int o = 16; o; o >>= 1) {
        a += __shfl_xor_sync(0xffffffffu, a, o);
        b += __shfl_xor_sync(0xffffffffu, b, o);
        c += __shfl_xor_sync(0xffffffffu, c, o);
    }
    __shared__ float sa[8], sb[8], sc[8];
    int w = tid >> 5, l = tid & 31;
    if (l == 0) { sa[w] = a; sb[w] = b; sc[w] = c; }
    __syncthreads();
    float ta = 0.f, tb = 0.f, tc = 0.f;
    #pragma unroll
    for (int i = 0; i < 8; i++) { ta += sa[i]; tb += sb[i]; tc += sc[i]; }
    float ia = rsqrtf(ta);
    float ib = rsqrtf(tb);
    if (tid == 0) g_diag[row] = tc * ia * ib;
    __nv_bfloat162 so = __float22bfloat162_rn(make_float2(sv.x * ia, sv.y * ia));
    __nv_bfloat162 to = __float22bfloat162_rn(make_float2(tv.x * ib, tv.y * ib));
    ((__nv_bfloat162*)g_sn)[(size_t)row * (DIM / 2) + tid] = so;
    ((__nv_bfloat162*)g_tn)[(size_t)row * (DIM / 2) + tid] = to;
}

// ===================== packed softplus pair, accumulated into eL/eS =====================
// reciprocal: chord seed (5/6 - d/6) + TWO Newton steps — R5-validated (~3e-6 max err).
#define EPI_PAIR(F0, F1) do { \
    u64 _pa = pack2(F0, F1); \
    u64 _x  = pfma(_pa, c_invT, c_negM); \
    u64 _ax = _x & 0x7FFFFFFF7FFFFFFFull; \
    u64 _t  = pmul(_ax, c_negL2E); \
    u64 _kf = padd(_t, c_magic); \
    u64 _f  = pfma(padd(_kf, c_nmagic), c_neg1, _t); \
    u64 _p  = pfma(c_e4, _f, c_e3); \
    _p = pfma(_p, _f, c_e2); \
    _p = pfma(_p, _f, c_e1); \
    _p = pfma(_p, _f, c_one); \
    uint32_t _klo, _khi, _plo, _phi; \
    unpack2(_klo, _khi, _kf); \
    unpack2(_plo, _phi, _p); \
    _plo += _klo << 23; \
    _phi += _khi << 23; \
    u64 _e; asm("mov.b64 %0, {%1, %2};" : "=l"(_e) : "r"(_plo), "r"(_phi)); \
    u64 _nd = pfma(_e, c_neg1, c_neg2); \
    u64 _y  = pfma(_nd, c_16, c_56); \
    _y = pmul(_y, pfma(_nd, _y, c_two)); \
    _y = pmul(_y, pfma(_nd, _y, c_two)); \
    u64 _z  = pmul(_e, _y); \
    u64 _z2 = pmul(_z, _z); \
    u64 _q  = pfma(c_q3, _z2, c_q2); \
    _q = pfma(_q, _z2, c_q1); \
    _q = pfma(_q, _z2, c_two); \
    eL = pfma(_z, _q, eL); \
    eS = padd(eS, _x); \
    eS = padd(eS, _ax); \
} while (0)

// mainloop over one 128x128 tile into ACC, with epilogue of PREV interleaved per k-step
#define DO_TILE(ACC, PREV) do { \
    _Pragma("unroll") \
    for (int _i = 0; _i < 64; ++_i) ACC[_i] = 0.f; \
    _Pragma("unroll") \
    for (int c = 0; c < 8; ++c) { \
        CP_WAIT(1); \
        __syncthreads(); \
        uint32_t aBase = sA + (uint32_t)(c & 1) * A_STAGE; \
        uint32_t bBase = sB + (uint32_t)c * A_STAGE; \
        _Pragma("unroll") \
        for (int ks = 0; ks < 4; ++ks) { \
            uint32_t afr[2][4]; \
            _Pragma("unroll") \
            for (int mi = 0; mi < 2; ++mi) { \
                int row = aRow + (mi << 4); \
                uint32_t kb = (uint32_t)(aKsel + (ks << 5)); \
                ldsm4(afr[mi], aBase + (row << 7) + (kb ^ ((row & 7) << 4))); \
            } \
            _Pragma("unroll") \
            for (int nb = 0; nb < 4; ++nb) { \
                uint32_t bfr[4]; \
                int row = bRow + (nb << 4); \
                uint32_t kb = (uint32_t)(bKsel + (ks << 5)); \
                ldsm4(bfr, bBase + (row << 7) + (kb ^ ((row & 7) << 4))); \
                _Pragma("unroll") \
                for (int mi = 0; mi < 2; ++mi) { \
                    mma16816(&ACC[((mi << 3) + (nb << 1)) << 2],     afr[mi], bfr[0], bfr[1]); \
                    mma16816(&ACC[((mi << 3) + (nb << 1) + 1) << 2], afr[mi], bfr[2], bfr[3]); \
                } \
            } \
            EPI_PAIR(PREV[((c << 2) + ks) * 2], PREV[((c << 2) + ks) * 2 + 1]); \
        } \
        __syncthreads(); \
        { \
            const uint8_t* psrc = (c < 6) ? gAc : gAn; \
            uint32_t pch = (c < 6) ? (uint32_t)(c + 2) : (uint32_t)(c - 6); \
            uint32_t pst = sA + (uint32_t)(c & 1) * A_STAGE; \
            _Pragma("unroll") \
            for (int _i = 0; _i < 4; ++_i) cp_async16(pst + soff[_i], psrc + gofs[_i] + pch * 128u); \
            CP_COMMIT(); \
        } \
    } \
    gAc = gAn; \
    t += GRIDX; \
    { int tnn = t + GRIDX; if (tnn >= NTILES) tnn = t; \
      gAn = (const uint8_t*)g_sn + ((size_t)(((tnn >> 10) << 3) + rband) << 17); } \
} while (0)

// ===================== kernel 2: persistent-col GEMM + pipelined softplus epilogue ============
// 256 threads (8 warps, 4x2), warp tile 32x64. B col-tile resident in SMEM (128KB),
// A row-tiles stream double-buffered. Epilogue of tile i runs inside mainloop of tile i+1.
__global__ __launch_bounds__(256, 1) void gemm_loss_kernel() {
    extern __shared__ uint8_t dynsmem[];
    __shared__ float s_red[8];

    int tid  = threadIdx.x;
    int wid  = tid >> 5;
    int lane = tid & 31;
    int bid  = blockIdx.x;

    uint32_t rbase = smem_u32(dynsmem);
    uint32_t base  = (rbase + 1023u) & ~1023u;
    uint32_t sB = base;                  // 8 resident B chunks
    uint32_t sA = base + B_BYTES;        // 2 A stages

    // this CTA: fixed col-tile bc, row-tiles t = bid + k*GRIDX
    int rband = bid & 7;
    int bc    = (bid & 1023) >> 3;
    int t     = bid;
    const uint8_t* gAc = (const uint8_t*)g_sn + ((size_t)(((t >> 10) << 3) + rband) << 17);
    const uint8_t* gAn = (const uint8_t*)g_sn + ((size_t)((((t + GRIDX) >> 10) << 3) + rband) << 17);
    const uint8_t* gB  = (const uint8_t*)g_tn + ((size_t)bc << 17);

    // per-thread cp.async slots: 4 x 16B covers one 16KB tile-chunk with 256 threads
    uint32_t soff[4], gofs[4];
    #pragma unroll
    for (int i = 0; i < 4; i++) {
        int idx = tid + (i << 8);
        int r   = idx >> 3, sg = idx & 7;
        soff[i] = SWZ((r << 7) + (sg << 4));
        gofs[i] = r * (DIM * 2) + (sg << 4);
    }

    // ldmatrix components (validated R4 mapping)
    int wm = wid & 3, wn = wid >> 2;
    int aRow  = (wm << 5) + (lane & 15);
    int aKsel = (lane >> 4) << 4;
    int bRow  = (wn << 6) + (lane & 7) + ((lane & 16) >> 1);
    int bKsel = (lane & 8) << 1;

    // epilogue constants (thread-invariant; expect UR promotion)
    const u64 c_invT   = bcast(INV_T);
    const u64 c_negM   = bcast(-MARGIN);
    const u64 c_negL2E = bcast(-1.4426950408889634f);
    const u64 c_magic  = bcast(12582912.0f);
    const u64 c_nmagic = bcast(-12582912.0f);
    const u64 c_neg1   = bcast(-1.0f);
    const u64 c_neg2   = bcast(-2.0f);
    const u64 c_two    = bcast(2.0f);
    const u64 c_e4     = bcast(9.6181291918e-3f);
    const u64 c_e3     = bcast(5.5504108664e-2f);
    const u64 c_e2     = bcast(2.4022650696e-1f);
    const u64 c_e1     = bcast(6.9314718056e-1f);
    const u64 c_one    = bcast(1.0f);
    const u64 c_16     = bcast(0.16666667f);   // chord seed: y = 5/6 - d/6
    const u64 c_56     = bcast(0.83333333f);
    const u64 c_q3     = bcast(0.28571429f);
    const u64 c_q2     = bcast(0.4f);
    const u64 c_q1     = bcast(0.66666667f);

    u64 eL = 0ull, eS = 0ull;
    float accA[64], accB[64];
    #pragma unroll
    for (int i = 0; i < 64; i++) accB[i] = 0.f;

    // ---- prologue: resident B (1 group), then A chunks 0,1 of first tile ----
    #pragma unroll
    for (int c = 0; c < 8; ++c)
        #pragma unroll
        for (int i = 0; i < 4; ++i)
            cp_async16(sB + (uint32_t)c * A_STAGE + soff[i], gB + gofs[i] + c * 128u);
    CP_COMMIT();
    #pragma unroll
    for (int i = 0; i < 4; ++i) cp_async16(sA + soff[i], gAc + gofs[i]);
    CP_COMMIT();
    #pragma unroll
    for (int i = 0; i < 4; ++i) cp_async16(sA + A_STAGE + soff[i], gAc + gofs[i] + 128u);
    CP_COMMIT();

    // ---- 8 tiles, banks alternating; epilogue of previous tile rides in the mainloop ----
    #pragma unroll 1
    for (int it = 0; it < 4; ++it) {
        DO_TILE(accA, accB);
        if (it == 0) { eL = 0ull; eS = 0ull; }   // discard epi of the zero bank
        DO_TILE(accB, accA);
    }
    CP_WAIT(0);

    // ---- final epilogue: last bank (accB) ----
    #pragma unroll
    for (int p = 0; p < 32; ++p) EPI_PAIR(accB[2 * p], accB[2 * p + 1]);

    // ---- reduce: one atomicAdd per CTA ----
    uint32_t slo, shi, llo, lhi;
    unpack2(slo, shi, eS);
    unpack2(llo, lhi, eL);
    float sum = __uint_as_float(llo) + __uint_as_float(lhi);
    sum = fmaf(__uint_as_float(slo) + __uint_as_float(shi), 0.5f, sum);

    #pragma unroll
    for (int o = 16; o; o >>= 1) sum += __shfl_xor_sync(0xffffffffu, sum, o);
    if (lane == 0) s_red[wid] = sum;
    __syncthreads();
    if (tid == 0) {
        float s = 0.f;
        #pragma unroll
        for (int i = 0; i < 8; i++) s += s_red[i];
        atomicAdd(&g_sum, (double)s);
    }
}

// ===================== kernel 3: diagonal correction + finalize =====================
__global__ __launch_bounds__(256) void finalize_kernel(float* out) {
    __shared__ float s_red[8];
    int tid = threadIdx.x;
    float corr = 0.f;
    for (int i = tid; i < NTOK; i += 256) {
        float l = g_diag[i] * INV_T;
        corr += softplus_fast(-l - MARGIN) - softplus_fast(l - MARGIN);
    }
    #pragma unroll
    for (int o = 16; o; o >>= 1) corr += __shfl_xor_sync(0xffffffffu, corr, o);
    int w = tid >> 5, l = tid & 31;
    if (l == 0) s_red[w] = corr;
    __syncthreads();
    if (tid == 0) {
        float tc = 0.f;
        #pragma unroll
        for (int i = 0; i < 8; i++) tc += s_red[i];
        out[0] = (float)((g_sum + (double)tc) * (1.0 / (double)NTOK));
    }
}

// ===================== launch =====================
extern "C" void kernel_launch(void* const* d_in, const int* in_sizes, int n_in,
                              void* d_out, int out_size) {
    const float* S = (const float*)d_in[0];
    const float* T = (const float*)d_in[1];
    cudaFuncSetAttribute(gemm_loss_kernel,
                         cudaFuncAttributeMaxDynamicSharedMemorySize, SMEM_SZ);
    normalize_kernel<<<NTOK, 256>>>(S, T);
    gemm_loss_kernel<<<GRIDX, 256, SMEM_SZ>>>();
    finalize_kernel<<<1, 256>>>((float*)d_out);
}